// round 11
// baseline (speedup 1.0000x reference)
#include <cuda_runtime.h>
#include <cuda_bf16.h>

// Problem constants
#define NTOK   4096      // B*S
#define DIN    2048
#define DOUT   2048
#define NEXP   16
#define RANK   16
#define TOPK   2
#define NASSIGN (NTOK*TOPK)   // 8192
#define ALPHA  2.0f
#define DSPLIT 8              // phase-A d-reduction split (4 chunks of 64 per block)
#define TILE_T 128            // tokens per tile
#define TPE    4              // static tile slots per expert (capacity 512 tokens)
#define WIN    64             // phase-B token window per block
#define GRP    2              // phase-B inner group

#define A_BUF_FLOATS (128 * 68 + 16 * 68)            // sx + sw per stage buffer
#define A_SMEM_BYTES (2 * A_BUF_FLOATS * 4)          // 78336 B dynamic

typedef unsigned long long ull;

// ---------------- packed f32x2 helpers (FFMA2 via PTX) ----------------
__device__ __forceinline__ void fma2(ull &acc, ull a, ull b) {
    asm("fma.rn.f32x2 %0, %1, %2, %0;" : "+l"(acc) : "l"(a), "l"(b));
}
__device__ __forceinline__ ull add2(ull a, ull b) {
    ull r; asm("add.rn.f32x2 %0, %1, %2;" : "=l"(r) : "l"(a), "l"(b)); return r;
}
__device__ __forceinline__ float hadd2(ull v) {
    float lo, hi; asm("mov.b64 {%0,%1}, %2;" : "=f"(lo), "=f"(hi) : "l"(v));
    return lo + hi;
}
__device__ __forceinline__ void cp16(void* smem, const void* gmem) {
    unsigned sa = (unsigned)__cvta_generic_to_shared(smem);
    asm volatile("cp.async.cg.shared.global [%0], [%1], 16;" :: "r"(sa), "l"(gmem));
}
#define CP_COMMIT()  asm volatile("cp.async.commit_group;")
#define CP_WAIT(n)   asm volatile("cp.async.wait_group %0;" :: "n"(n))
__device__ __forceinline__ void red_v4(float* p, float a, float b, float c, float d) {
    asm volatile("red.global.add.v4.f32 [%0], {%1, %2, %3, %4};"
                 :: "l"(p), "f"(a), "f"(b), "f"(c), "f"(d) : "memory");
}

// ---------------- device scratch ----------------
__device__ int   d_run[32];                  // per-(k,e) counts (written by scatter owners)
__device__ int   d_list[2][NEXP * NTOK];     // bucketed token ids: [k][e*NTOK + pos]
__device__ float d_part[DSPLIT][NASSIGN * RANK];  // phase-A partial dots

// ---------------- kernel 1: bucket-ownership scatter (no atomics, no memset) ----------------
// 32 blocks; block c owns bucket (k = c>>4, e = c&15). Scans all 4096 k-indices,
// ballot-compacts matches. Order within bucket is irrelevant downstream (RED accum).
__global__ __launch_bounds__(256) void scatter_kernel(const int* __restrict__ idxs) {
    __shared__ int s_cnt;
    int c = blockIdx.x;
    int k = c >> 4, e = c & 15;
    int tid = threadIdx.x, lane = tid & 31;
    if (tid == 0) s_cnt = 0;
    __syncthreads();
    int* lst = &d_list[k][e * NTOK];
#pragma unroll
    for (int it = 0; it < NTOK / 256; it++) {       // 16 iterations
        int t = it * 256 + tid;
        bool m = (idxs[2 * t + k] & 15) == e;
        unsigned mask = __ballot_sync(0xffffffffu, m);
        if (mask) {
            int ldr = __ffs(mask) - 1;
            int base = 0;
            if (lane == ldr) base = atomicAdd(&s_cnt, __popc(mask));
            base = __shfl_sync(0xffffffffu, base, ldr);
            if (m) lst[base + __popc(mask & ((1u << lane) - 1u))] = t;
        }
    }
    __syncthreads();
    if (tid == 0) d_run[c] = s_cnt;
}

// ---------------- kernel 2: phase A — cp.async pipelined + fused out-zeroing ----------------
// grid (NEXP*TPE, 2, DSPLIT), block 256: 2 threads/token, rh = odd/even ranks.
__global__ __launch_bounds__(256) void phaseA_kernel(const float* __restrict__ x,
                                                     const float* __restrict__ w_a,
                                                     float* __restrict__ out) {
    int tid = threadIdx.x;

    // zero this block's slice of out (32MB / 1024 blocks = 8192 floats), BEFORE early return
    {
        int bid = blockIdx.x + (NEXP * TPE) * (blockIdx.y + 2 * blockIdx.z);  // 0..1023
        float4* oz = (float4*)out + (size_t)bid * 2048;
        float4 z = make_float4(0.f, 0.f, 0.f, 0.f);
#pragma unroll
        for (int i = 0; i < 8; i++) oz[i * 256 + tid] = z;
    }

    int k  = blockIdx.y;
    int ti = blockIdx.x;
    int e   = ti >> 2;             // expert
    int sub = ti & 3;              // tile slot within expert
    int cnt = d_run[k * 16 + e];
    int t0i = sub * TILE_T;
    int cl  = cnt - t0i;
    if (cl <= 0) return;
    if (cl > TILE_T) cl = TILE_T;
    int start = e * NTOK + t0i;
    int ds = blockIdx.z;

    extern __shared__ float dyn[];           // 2 x (sx[128*68] + sw[16*68])
    __shared__ int s_tok[128];

    int j2  = tid >> 1;        // token slot
    int rh  = tid & 1;         // rank parity: handles ranks {2i+rh}

    if (tid < 128) {
        int jcl = tid < cl ? tid : (cl - 1);
        s_tok[tid] = d_list[k][start + jcl];
    }
    __syncthreads();

    const float* wa_e = w_a + (size_t)e * RANK * DIN;
    int dbase0 = ds * (DIN / DSPLIT);        // 256-wide slice, 4 chunks of 64

    auto stage = [&](int buf, int ch) {
        float* sxb = dyn + buf * A_BUF_FLOATS;
        float* swb = sxb + 128 * 68;
        int db = dbase0 + ch * 64;
#pragma unroll
        for (int it = 0; it < 8; it++) {
            int l = it * 256 + tid;
            int tok = l >> 4, c4 = l & 15;
            cp16(sxb + tok * 68 + c4 * 4,
                 x + (size_t)s_tok[tok] * DIN + db + c4 * 4);
        }
        {
            int r = tid >> 4, c4 = tid & 15;
            cp16(swb + r * 68 + c4 * 4,
                 wa_e + (size_t)r * DIN + db + c4 * 4);
        }
        CP_COMMIT();
    };

    ull acc[8];
#pragma unroll
    for (int i = 0; i < 8; i++) acc[i] = 0ull;

    stage(0, 0);
    int buf = 0;
#pragma unroll
    for (int ch = 0; ch < 4; ch++) {
        if (ch < 3) { stage(buf ^ 1, ch + 1); CP_WAIT(1); }
        else        { CP_WAIT(0); }
        __syncthreads();

        const float* sxb = dyn + buf * A_BUF_FLOATS;
        const float* swb = sxb + 128 * 68;
        const float* sxr = sxb + j2 * 68;
        const float* swr = swb + rh * 68;    // rank 2i+rh at row offset (2i+rh)*68
#pragma unroll
        for (int c4 = 0; c4 < 16; c4++) {
            ulonglong2 xv = *(const ulonglong2*)(sxr + c4 * 4);
#pragma unroll
            for (int i = 0; i < 8; i++) {
                ulonglong2 wv = *(const ulonglong2*)(swr + (2 * i) * 68 + c4 * 4);
                fma2(acc[i], xv.x, wv.x);
                fma2(acc[i], xv.y, wv.y);
            }
        }
        __syncthreads();
        buf ^= 1;
    }

    if (j2 < cl) {
        int a = s_tok[j2] * 2 + k;
        float* p = &d_part[ds][(size_t)a * RANK];
#pragma unroll
        for (int i = 0; i < 8; i++) p[2 * i + rh] = hadd2(acc[i]);
    }
}

// ---------------- kernel 3: phase B — 4 consecutive d/thread, one red.v4 per token ----------------
// grid (NEXP*TPE, DOUT/512, 4), block 128. z = (zslice<<1)|k.
__global__ __launch_bounds__(128) void phaseB_kernel(const float* __restrict__ w_b,
                                                     const float* __restrict__ routing,
                                                     float* __restrict__ out) {
    int kk = blockIdx.z & 1;
    int zs = blockIdx.z >> 1;
    int ti = blockIdx.x;
    int e   = ti >> 2;
    int sub = ti & 3;
    int cnt = d_run[kk * 16 + e];
    int t0i = sub * TILE_T + zs * WIN;
    int cl  = cnt - t0i;
    if (cl <= 0) return;
    if (cl > WIN) cl = WIN;
    int start = e * NTOK + t0i;

    __shared__ float sg[WIN * 16];
    __shared__ int   s_tok[WIN];

    int tid = threadIdx.x;
    if (tid < WIN) {
        int jcl = tid < cl ? tid : (cl - 1);
        s_tok[tid] = d_list[kk][start + jcl];
    }
    // stage g with fused DSPLIT-combine + silu*routing*alpha: 64 tok x 4 quads over 128 thr
#pragma unroll
    for (int it = 0; it < 2; it++) {
        int l = it * 128 + tid;
        int j = l >> 2, q = l & 3;
        int jcl = j < cl ? j : (cl - 1);
        int t = d_list[kk][start + jcl];
        int a = t * 2 + kk;
        size_t off = (size_t)a * RANK + q * 4;
        float4 s = *(const float4*)(&d_part[0][off]);
#pragma unroll
        for (int ds = 1; ds < DSPLIT; ds++) {
            float4 p = *(const float4*)(&d_part[ds][off]);
            s.x += p.x; s.y += p.y; s.z += p.z; s.w += p.w;
        }
        float rs = routing[a] * ALPHA;
        float4 g;
        g.x = rs * s.x * (1.0f / (1.0f + __expf(-s.x)));
        g.y = rs * s.y * (1.0f / (1.0f + __expf(-s.y)));
        g.z = rs * s.z * (1.0f / (1.0f + __expf(-s.z)));
        g.w = rs * s.w * (1.0f / (1.0f + __expf(-s.w)));
        *(float4*)(sg + j * 16 + q * 4) = g;
    }
    __syncthreads();

    int d0 = blockIdx.y * 512 + tid * 4;     // 4 consecutive outputs per thread (16B aligned)
    const ulonglong2* w0p = (const ulonglong2*)(w_b + ((size_t)e * DOUT + d0 + 0) * RANK);
    const ulonglong2* w1p = (const ulonglong2*)(w_b + ((size_t)e * DOUT + d0 + 1) * RANK);
    const ulonglong2* w2p = (const ulonglong2*)(w_b + ((size_t)e * DOUT + d0 + 2) * RANK);
    const ulonglong2* w3p = (const ulonglong2*)(w_b + ((size_t)e * DOUT + d0 + 3) * RANK);
    ulonglong2 wA0 = w0p[0], wA1 = w0p[1], wA2 = w0p[2], wA3 = w0p[3];
    ulonglong2 wB0 = w1p[0], wB1 = w1p[1], wB2 = w1p[2], wB3 = w1p[3];
    ulonglong2 wC0 = w2p[0], wC1 = w2p[1], wC2 = w2p[2], wC3 = w2p[3];
    ulonglong2 wD0 = w3p[0], wD1 = w3p[1], wD2 = w3p[2], wD3 = w3p[3];

    for (int j0 = 0; j0 < cl; j0 += GRP) {
        float rA[GRP], rB[GRP], rC[GRP], rD[GRP];
#pragma unroll
        for (int u = 0; u < GRP; u++) {
            int jj = j0 + u; if (jj >= cl) jj = cl - 1;
            const ulonglong2* g = (const ulonglong2*)(sg + jj * 16);
            ulonglong2 ga = g[0], gb = g[1], gc = g[2], gd = g[3];
            ull a0 = 0ull, a1 = 0ull, b0 = 0ull, b1 = 0ull;
            ull c0 = 0ull, c1 = 0ull, e0 = 0ull, e1 = 0ull;
            fma2(a0, ga.x, wA0.x); fma2(a1, ga.y, wA0.y);
            fma2(b0, ga.x, wB0.x); fma2(b1, ga.y, wB0.y);
            fma2(c0, ga.x, wC0.x); fma2(c1, ga.y, wC0.y);
            fma2(e0, ga.x, wD0.x); fma2(e1, ga.y, wD0.y);
            fma2(a0, gb.x, wA1.x); fma2(a1, gb.y, wA1.y);
            fma2(b0, gb.x, wB1.x); fma2(b1, gb.y, wB1.y);
            fma2(c0, gb.x, wC1.x); fma2(c1, gb.y, wC1.y);
            fma2(e0, gb.x, wD1.x); fma2(e1, gb.y, wD1.y);
            fma2(a0, gc.x, wA2.x); fma2(a1, gc.y, wA2.y);
            fma2(b0, gc.x, wB2.x); fma2(b1, gc.y, wB2.y);
            fma2(c0, gc.x, wC2.x); fma2(c1, gc.y, wC2.y);
            fma2(e0, gc.x, wD2.x); fma2(e1, gc.y, wD2.y);
            fma2(a0, gd.x, wA3.x); fma2(a1, gd.y, wA3.y);
            fma2(b0, gd.x, wB3.x); fma2(b1, gd.y, wB3.y);
            fma2(c0, gd.x, wC3.x); fma2(c1, gd.y, wC3.y);
            fma2(e0, gd.x, wD3.x); fma2(e1, gd.y, wD3.y);
            rA[u] = hadd2(add2(a0, a1));
            rB[u] = hadd2(add2(b0, b1));
            rC[u] = hadd2(add2(c0, c1));
            rD[u] = hadd2(add2(e0, e1));
        }
#pragma unroll
        for (int u = 0; u < GRP; u++) {
            int jj = j0 + u;
            if (jj < cl) {
                float* o = out + (size_t)s_tok[jj] * DOUT + d0;
                red_v4(o, rA[u], rB[u], rC[u], rD[u]);
            }
        }
    }
}

// ---------------- launcher ----------------
extern "C" void kernel_launch(void* const* d_in, const int* in_sizes, int n_in,
                              void* d_out, int out_size) {
    const float* x       = (const float*)d_in[0];
    const float* routing = (const float*)d_in[1];
    const int*   idxs    = (const int*)d_in[2];   // int32 (JAX x64 disabled)
    const float* w_a     = (const float*)d_in[3];
    const float* w_b     = (const float*)d_in[4];
    float*       out     = (float*)d_out;

    cudaFuncSetAttribute(phaseA_kernel, cudaFuncAttributeMaxDynamicSharedMemorySize,
                         A_SMEM_BYTES);

    scatter_kernel<<<32, 256>>>(idxs);
    phaseA_kernel<<<dim3(NEXP * TPE, 2, DSPLIT), 256, A_SMEM_BYTES>>>(x, w_a, out);
    phaseB_kernel<<<dim3(NEXP * TPE, DOUT / 512, 4), 128>>>(w_b, routing, out);
}